// round 3
// baseline (speedup 1.0000x reference)
#include <cuda_runtime.h>
#include <math.h>

#define B_   32
#define S_   4096
#define H_   768
#define D_   192
#define NS   15
#define NP   16
#define NSC  8          // s-split in pass B

#define INV_SCALE 0.072168783648703220563f   // 1/sqrt(192)
#define LOG_S     8.3177661667193433f        // log(4096)

// ------------------------------------------------------------------
// scratch (device globals; no allocation allowed)
// ------------------------------------------------------------------
__device__ float g_qk[NP * H_];              // [n][h], pre-scaled by 1/sqrt(d)
__device__ float g_qb[NP];                   // q . bk, pre-scaled
__device__ float g_w[B_ * NS * S_];          // exp(logit), unnormalized
__device__ float g_Z[B_ * NP];               // sum exp
__device__ float g_L[B_ * NP];               // sum exp * logit
__device__ float g_Tp[B_ * NSC * NP * H_];   // partial weighted x sums

// packed f32x2 FMA (Blackwell): d = a*b + c elementwise on 2 packed floats
__device__ __forceinline__ float2 ffma2(float2 a, float2 b, float2 c) {
    float2 d;
    asm("fma.rn.f32x2 %0, %1, %2, %3;"
        : "=l"(reinterpret_cast<unsigned long long&>(d))
        : "l"(reinterpret_cast<unsigned long long&>(a)),
          "l"(reinterpret_cast<unsigned long long&>(b)),
          "l"(reinterpret_cast<unsigned long long&>(c)));
    return d;
}

// ------------------------------------------------------------------
// prep: qk[n][h] = (Wk @ q_n)[h]/sqrt(d),  qb[n] = q_n.bk/sqrt(d); zero Z/L
// grid 48 x 256 = 12288 threads (one per (h, n-slot))
// ------------------------------------------------------------------
__global__ void prep_kernel(const float* __restrict__ SQ,
                            const float* __restrict__ Wk,
                            const float* __restrict__ bk) {
    int idx = blockIdx.x * 256 + threadIdx.x;   // 0..12287
    int h = idx >> 4, n = idx & 15;
    float v = 0.f;
    if (n < NS) {
        float s = 0.f;
        const float* q = SQ + n * D_;
        const float* w = Wk + h * D_;
#pragma unroll 8
        for (int d = 0; d < D_; d++) s += q[d] * w[d];
        v = s * INV_SCALE;
    }
    g_qk[n * H_ + h] = v;
    if (idx < NP) {
        float s = 0.f;
        if (idx < NS) {
            const float* q = SQ + idx * D_;
            for (int d = 0; d < D_; d++) s += q[d] * bk[d];
        }
        g_qb[idx] = s * INV_SCALE;
    }
    if (idx < B_ * NP) { g_Z[idx] = 0.f; g_L[idx] = 0.f; }
}

// ------------------------------------------------------------------
// pass A: logits + exp + Z/L partials. grid (16 schunks, 32 b), 128 thr.
// Block covers 256 tokens x 16 signal-slots. Thread tile: 8 tok x 4 sig.
// ------------------------------------------------------------------
__global__ __launch_bounds__(128) void pass_a(const float* __restrict__ X) {
    const int b  = blockIdx.y;
    const int s0 = blockIdx.x << 8;
    const int tid  = threadIdx.x;
    const int sgrp = tid & 3;        // 4 signal groups of 4
    const int tgrp = tid >> 2;       // 32 token groups; tokens tgrp + 32*i

    __shared__ float xs[256 * 34];   // stride 34: conflict-free LDS.64
    __shared__ float qks[16 * 34];
    __shared__ float zs[16], ls[16];

    float2 acc[8][4];
#pragma unroll
    for (int i = 0; i < 8; i++)
#pragma unroll
        for (int j = 0; j < 4; j++) acc[i][j] = make_float2(0.f, 0.f);

    const float* xbase = X + (size_t)(b * S_ + s0) * H_;

    for (int hc = 0; hc < H_; hc += 32) {
        // stage qk chunk [16][32]
        for (int idx = tid; idx < 512; idx += 128) {
            int n = idx >> 5, hh = idx & 31;
            qks[n * 34 + hh] = g_qk[n * H_ + hc + hh];
        }
        // stage x tile [256 tok][32 h], coalesced
#pragma unroll 8
        for (int k = 0; k < 64; k++) {
            int idx = tid + (k << 7);
            int tok = idx >> 5, hh = idx & 31;
            xs[tok * 34 + hh] = xbase[tok * H_ + hc + hh];
        }
        __syncthreads();
#pragma unroll
        for (int h2 = 0; h2 < 16; h2++) {
            float2 qv[4];
#pragma unroll
            for (int j = 0; j < 4; j++)
                qv[j] = *(const float2*)&qks[(sgrp * 4 + j) * 34 + h2 * 2];
#pragma unroll
            for (int i = 0; i < 8; i++) {
                float2 xv = *(const float2*)&xs[(tgrp + (i << 5)) * 34 + h2 * 2];
#pragma unroll
                for (int j = 0; j < 4; j++) acc[i][j] = ffma2(xv, qv[j], acc[i][j]);
            }
        }
        __syncthreads();
    }

    if (tid < 16) { zs[tid] = 0.f; ls[tid] = 0.f; }
    __syncthreads();

    float qb[4];
#pragma unroll
    for (int j = 0; j < 4; j++) qb[j] = g_qb[sgrp * 4 + j];

    float zp[4] = {0.f, 0.f, 0.f, 0.f}, lp[4] = {0.f, 0.f, 0.f, 0.f};
#pragma unroll
    for (int i = 0; i < 8; i++) {
        int s = s0 + tgrp + (i << 5);
#pragma unroll
        for (int j = 0; j < 4; j++) {
            int n = sgrp * 4 + j;
            float l = acc[i][j].x + acc[i][j].y + qb[j];
            float w = __expf(l);
            zp[j] += w;
            lp[j] += w * l;
            if (n < NS) g_w[(size_t)(b * NS + n) * S_ + s] = w;
        }
    }
#pragma unroll
    for (int j = 0; j < 4; j++) {
        atomicAdd(&zs[sgrp * 4 + j], zp[j]);
        atomicAdd(&ls[sgrp * 4 + j], lp[j]);
    }
    __syncthreads();
    if (tid < 16) {
        atomicAdd(&g_Z[b * NP + tid], zs[tid]);
        atomicAdd(&g_L[b * NP + tid], ls[tid]);
    }
}

// ------------------------------------------------------------------
// pass B: Tp[b][sc][n][h] = sum_{s in chunk} w[b,n,s] * x[b,s,h]
// grid (8 schunks, 3 hchunks, 32 b), 128 threads. Thread owns an h pair.
// ------------------------------------------------------------------
__global__ __launch_bounds__(128) void pass_b(const float* __restrict__ X) {
    const int sc  = blockIdx.x;      // 0..7
    const int hcb = blockIdx.y;      // 0..2
    const int b   = blockIdx.z;
    const int tid = threadIdx.x;
    const int h0  = hcb * 256;
    const int sbeg = sc * 512;

    __shared__ float2 ws2[NS * 64];  // {w,w} packed, per 64-token tile

    float2 acc[NS];
#pragma unroll
    for (int n = 0; n < NS; n++) acc[n] = make_float2(0.f, 0.f);

    const float* xp = X + (size_t)(b * S_ + sbeg) * H_ + h0 + tid * 2;

    for (int t = 0; t < 8; t++) {
        int st = sbeg + t * 64;
        __syncthreads();
        for (int idx = tid; idx < NS * 64; idx += 128) {
            int n = idx >> 6, si = idx & 63;
            float w = g_w[(size_t)(b * NS + n) * S_ + st + si];
            ws2[n * 64 + si] = make_float2(w, w);
        }
        __syncthreads();
#pragma unroll 4
        for (int si = 0; si < 64; si++) {
            float2 xv = *(const float2*)xp;
            xp += H_;
#pragma unroll
            for (int n = 0; n < NS; n++)
                acc[n] = ffma2(ws2[n * 64 + si], xv, acc[n]);
        }
    }
#pragma unroll
    for (int n = 0; n < NS; n++) {
        *(float2*)&g_Tp[(size_t)((b * NSC + sc) * NP + n) * H_ + h0 + tid * 2] = acc[n];
    }
}

// ------------------------------------------------------------------
// finalize: combine partials, entropy/strength, signal_embed = t@Wv+bv,
// MLP head (exact gelu). grid (4 ngroups, 32 b), 192 threads.
// ------------------------------------------------------------------
__global__ __launch_bounds__(192) void finalize_kernel(
    const float* __restrict__ Wv, const float* __restrict__ bv,
    const float* __restrict__ NE, const float* __restrict__ W1,
    const float* __restrict__ b1, const float* __restrict__ W2,
    const float* __restrict__ b2, float* __restrict__ out) {
    const int ng = blockIdx.x;       // 0..3
    const int b  = blockIdx.y;
    const int tid = threadIdx.x;     // <192
    const int nbeg = ng * 4;
    const int kcnt = (NS - nbeg < 4) ? (NS - nbeg) : 4;

    __shared__ float ts[4 * H_];
    __shared__ float effs[4][2 * D_];
    __shared__ float gh[64];

    for (int k = 0; k < 4; k++) {
        int n = nbeg + k;
        if (k < kcnt) {
            float Z = g_Z[b * NP + n];
            float invZ = 1.0f / Z;
#pragma unroll
            for (int r = 0; r < 4; r++) {
                int h = tid + r * 192;
                float T = 0.f;
#pragma unroll
                for (int scc = 0; scc < NSC; scc++)
                    T += g_Tp[(size_t)((b * NSC + scc) * NP + n) * H_ + h];
                ts[k * H_ + h] = T * invZ;
            }
            if (tid == 0) {
                float ent = logf(Z) - g_L[b * NP + n] * invZ;
                out[b * (2 * NS) + NS + n] = 1.0f - ent * (1.0f / LOG_S);
            }
        } else {
#pragma unroll
            for (int r = 0; r < 4; r++) ts[k * H_ + tid + r * 192] = 0.f;
        }
    }
    __syncthreads();

    // signal embeds for 4 signals simultaneously (single Wv sweep);
    // thread tid owns output dim d = tid
    float se0 = bv[tid], se1 = se0, se2 = se0, se3 = se0;
#pragma unroll 4
    for (int h = 0; h < H_; h++) {
        float wv = Wv[h * D_ + tid];
        se0 = fmaf(ts[0 * H_ + h], wv, se0);
        se1 = fmaf(ts[1 * H_ + h], wv, se1);
        se2 = fmaf(ts[2 * H_ + h], wv, se2);
        se3 = fmaf(ts[3 * H_ + h], wv, se3);
    }
    effs[0][tid] = se0; effs[1][tid] = se1; effs[2][tid] = se2; effs[3][tid] = se3;
    for (int k = 0; k < 4; k++)
        effs[k][D_ + tid] = (k < kcnt) ? NE[(size_t)(nbeg + k) * H_ + tid] : 0.f;
    __syncthreads();

    for (int k = 0; k < kcnt; k++) {
        if (tid < 64) {
            float hs = b1[tid];
#pragma unroll 4
            for (int i = 0; i < 2 * D_; i++)
                hs = fmaf(effs[k][i], W1[i * 64 + tid], hs);
            // exact gelu: 0.5*x*(1+erf(x/sqrt(2)))
            gh[tid] = 0.5f * hs * (1.0f + erff(hs * 0.70710678118654752f));
        }
        __syncthreads();
        if (tid == 0) {
            float e = b2[0];
            for (int i = 0; i < 64; i++) e = fmaf(gh[i], W2[i], e);
            out[b * (2 * NS) + nbeg + k] = e;
        }
        __syncthreads();
    }
}

// ------------------------------------------------------------------
extern "C" void kernel_launch(void* const* d_in, const int* in_sizes, int n_in,
                              void* d_out, int out_size) {
    const float* X   = (const float*)d_in[0];   // token_embeds [32,4096,768]
    const float* Wk  = (const float*)d_in[1];   // [768,192]
    const float* bk  = (const float*)d_in[2];   // [192]
    const float* Wv  = (const float*)d_in[3];   // [768,192]
    const float* bv  = (const float*)d_in[4];   // [192]
    const float* SQ  = (const float*)d_in[5];   // [15,192]
    const float* NE  = (const float*)d_in[6];   // [15,768]
    const float* W1  = (const float*)d_in[7];   // [384,64]
    const float* b1  = (const float*)d_in[8];   // [64]
    const float* W2  = (const float*)d_in[9];   // [64,1]
    const float* b2  = (const float*)d_in[10];  // [1]
    float* out = (float*)d_out;                 // [32,30]

    prep_kernel<<<48, 256>>>(SQ, Wk, bk);
    pass_a<<<dim3(16, B_), 128>>>(X);
    pass_b<<<dim3(NSC, 3, B_), 128>>>(X);
    finalize_kernel<<<dim3(4, B_), 192>>>(Wv, bv, NE, W1, b1, W2, b2, out);
}